// round 4
// baseline (speedup 1.0000x reference)
#include <cuda_runtime.h>
#include <cstdint>

#define Tt   200
#define Dd   128
#define CLS  8            // CTAs per cluster
#define RPC  16           // batch rows per cluster
#define NTHR 256
#define NBLK 128          // 16 clusters * 8

typedef unsigned long long u64;

// ---------------- smem layout (float indices) ----------------
#define SW_F     (320*32*4)            // 40960: gate weights, ulonglong2[k*32+hl]
#define OFF_U    SW_F                  // 40960: u [16][388]  (z|zp|x_i)
#define U_STR    388
#define OFF_LS   (OFF_U + RPC*U_STR)   // 47168: ls [16][68]
#define LS_STR   68
#define OFF_H    (OFF_LS + RPC*LS_STR) // 48256: h  [2][16][260]
#define H_STR    260
#define H_BUF    (RPC*H_STR)           // 4160
#define OFF_PB   (OFF_H + 2*H_BUF)     // 56576: B partials [128][2]
#define OFF_MISC (OFF_PB + 256)        // 56832: wzd|bz|wzpd|bzp|bfc (5*128)
#define SMEM_F   (OFF_MISC + 640)      // 57472
#define SMEM_BYTES (SMEM_F*4)          // 229888 B (< 227KB limit)

// ---------------- device globals (no allocs allowed) ----------------
__device__ __align__(16) float  g_WgT[320*256*4];   // [k][h] float4 = (Wi,Wf,Wo,Wc)[h][k]
__device__ __align__(8)  float2 g_Wq2[64*192];      // [m][kp] = (Wq[m][2kp], Wq[m][2kp+1])
__device__ __align__(8)  float2 g_Wfc2[128*128];    // [o][hp] = (Wfc[o][2hp], Wfc[o][2hp+1])
__device__ float g_wzd[128], g_wzpd[128];

__global__ void prep_kernel(const float* __restrict__ Wz,  const float* __restrict__ Wzp,
                            const float* __restrict__ Wq,  const float* __restrict__ Wi,
                            const float* __restrict__ Wf,  const float* __restrict__ Wo,
                            const float* __restrict__ Wc,  const float* __restrict__ Wfc)
{
    int idx = blockIdx.x * blockDim.x + threadIdx.x;   // 0 .. 81919
    if (idx < 320 * 256) {
        int k = idx >> 8, h = idx & 255;
        float4 w;
        w.x = Wi[h * 320 + k];
        w.y = Wf[h * 320 + k];
        w.z = Wo[h * 320 + k];
        w.w = Wc[h * 320 + k];
        reinterpret_cast<float4*>(g_WgT)[idx] = w;
    }
    if (idx < 64 * 192) {
        int m = idx / 192, kp = idx % 192;
        g_Wq2[idx] = make_float2(Wq[m * 384 + 2 * kp], Wq[m * 384 + 2 * kp + 1]);
    }
    if (idx < 128 * 128) {
        int o = idx >> 7, hp = idx & 127;
        g_Wfc2[idx] = make_float2(Wfc[o * 256 + 2 * hp], Wfc[o * 256 + 2 * hp + 1]);
    }
    if (idx < 128) {
        g_wzd[idx]  = Wz[idx * 128 + idx];
        g_wzpd[idx] = Wzp[idx * 128 + idx];
    }
}

// ---------------- helpers ----------------
__device__ __forceinline__ float fast_sigmoid(float x) { return 1.0f / (1.0f + __expf(-x)); }
__device__ __forceinline__ float fast_tanh(float x)    { return 1.0f - 2.0f / (__expf(2.0f * x) + 1.0f); }

__device__ __forceinline__ u64 pack2(float lo, float hi) {
    u64 r; asm("mov.b64 %0, {%1, %2};" : "=l"(r) : "f"(lo), "f"(hi)); return r;
}
__device__ __forceinline__ u64 dup2(float v) {
    u64 r; asm("mov.b64 %0, {%1, %1};" : "=l"(r) : "f"(v)); return r;
}
__device__ __forceinline__ void unpack2(u64 v, float& lo, float& hi) {
    asm("mov.b64 {%0, %1}, %2;" : "=f"(lo), "=f"(hi) : "l"(v));
}
__device__ __forceinline__ void fma2(u64& d, u64 a, u64 b) {
    asm("fma.rn.f32x2 %0, %1, %2, %0;" : "+l"(d) : "l"(a), "l"(b));
}
__device__ __forceinline__ uint32_t mapa_u32(uint32_t a, uint32_t r) {
    uint32_t d; asm("mapa.shared::cluster.u32 %0, %1, %2;" : "=r"(d) : "r"(a), "r"(r)); return d;
}
__device__ __forceinline__ void stc(uint32_t a, float v) {
    asm volatile("st.shared::cluster.f32 [%0], %1;" :: "r"(a), "f"(v));
}
__device__ __forceinline__ void cluster_sync_() {
    asm volatile("barrier.cluster.arrive.aligned;" ::: "memory");
    asm volatile("barrier.cluster.wait.aligned;"   ::: "memory");
}

// 4-k gate FMA body: 4 weight ulonglong2 (stride 32), comb quads for 2 rows
#define CBODY(P0, P1, WP) do { \
    ulonglong2 w0 = (WP)[0], w1 = (WP)[32], w2v = (WP)[64], w3 = (WP)[96]; \
    float4 ca = *reinterpret_cast<const float4*>(P0); \
    float4 cbv = *reinterpret_cast<const float4*>(P1); \
    u64 d; \
    d = dup2(ca.x);  fma2(aif0, w0.x,  d); fma2(aoc0, w0.y,  d); \
    d = dup2(ca.y);  fma2(aif0, w1.x,  d); fma2(aoc0, w1.y,  d); \
    d = dup2(ca.z);  fma2(aif0, w2v.x, d); fma2(aoc0, w2v.y, d); \
    d = dup2(ca.w);  fma2(aif0, w3.x,  d); fma2(aoc0, w3.y,  d); \
    d = dup2(cbv.x); fma2(aif1, w0.x,  d); fma2(aoc1, w0.y,  d); \
    d = dup2(cbv.y); fma2(aif1, w1.x,  d); fma2(aoc1, w1.y,  d); \
    d = dup2(cbv.z); fma2(aif1, w2v.x, d); fma2(aoc1, w2v.y, d); \
    d = dup2(cbv.w); fma2(aif1, w3.x,  d); fma2(aoc1, w3.y,  d); \
} while (0)

__global__ __launch_bounds__(NTHR, 1) __cluster_dims__(CLS, 1, 1)
void lgnet_kernel(
    const float* __restrict__ inp,    // [B,6,T,D]
    const float* __restrict__ xmean,  // [B,T,D]
    const float* __restrict__ bz,  const float* __restrict__ bzp,
    const float* __restrict__ bq,
    const float* __restrict__ bi,  const float* __restrict__ bf,
    const float* __restrict__ bo,  const float* __restrict__ bc,
    const float* __restrict__ bfc,
    float* __restrict__ out)          // [B,T,O]
{
    extern __shared__ __align__(16) float sm[];
    const int tid = threadIdx.x;
    uint32_t rank; asm("mov.u32 %0, %%cluster_ctarank;" : "=r"(rank));
    const int b0 = (blockIdx.x / CLS) * RPC;

    // ---- load this CTA's gate-weight slice (h in [32*rank, 32*rank+32)) into SMEM ----
    {
        const float4* __restrict__ g4 = reinterpret_cast<const float4*>(g_WgT);
        float4* s4 = reinterpret_cast<float4*>(sm);
        for (int i = tid; i < 320 * 32; i += NTHR) {
            int k = i >> 5, hl = i & 31;
            s4[i] = g4[k * 256 + rank * 32 + hl];       // smem [k][hl]
        }
    }
    // ---- misc + state init ----
    if (tid < 128) {
        sm[OFF_MISC +   0 + tid] = g_wzd[tid];
        sm[OFF_MISC + 128 + tid] = bz[tid];
        sm[OFF_MISC + 256 + tid] = g_wzpd[tid];
        sm[OFF_MISC + 384 + tid] = bzp[tid];
        sm[OFF_MISC + 512 + tid] = bfc[tid];
    }
    for (int i = tid; i < 2 * H_BUF; i += NTHR) sm[OFF_H + i] = 0.0f;   // h0 = 0
    for (int i = tid; i < RPC * 128; i += NTHR) {
        int row = i >> 7, o = i & 127;
        sm[OFF_U + row * U_STR + 256 + o] = bfc[o];                      // x_i_0 = bfc
    }

    // thread-stationary gate biases: h_global = 32*rank + (tid>>3)
    const int hg = (int)(rank << 5) + (tid >> 3);
    const u64 bias_if = pack2(bi[hg], bf[hg]);
    const u64 bias_oc = pack2(bo[hg], bc[hg]);
    float c_reg0 = 0.0f, c_reg1 = 0.0f;

    // peer smem base addresses for DSMEM multicast
    uint32_t sb;
    { u64 tmp; asm("cvta.to.shared.u64 %0, %1;" : "=l"(tmp) : "l"(sm)); sb = (uint32_t)tmp; }
    uint32_t pb[CLS];
#pragma unroll
    for (int r = 0; r < CLS; r++) pb[r] = mapa_u32(sb, (uint32_t)r);

    cluster_sync_();   // weights + init visible, peers ready to receive pushes

    for (int t = 0; t < Tt; t++) {
        const int cur = t & 1, prv = cur ^ 1;

        // ---------- Phase A: z, zp for all 16 cluster rows (redundant per CTA) ----------
        {
            const float* wzd = sm + OFF_MISC, *bzs = sm + OFF_MISC + 128;
            const float* wzp = sm + OFF_MISC + 256, *bzps = sm + OFF_MISC + 384;
            const long cs = (long)Tt * Dd;
            for (int e = tid; e < RPC * 128; e += NTHR) {
                int row = e >> 7, j = e & 127;
                long grow = b0 + row;
                long base = ((grow * 6) * Tt + t) * (long)Dd + j;
                float x   = inp[base];
                float xl  = inp[base + 1 * cs];
                float mk  = inp[base + 2 * cs];
                float dl  = inp[base + 3 * cs];
                float xlb = inp[base + 4 * cs];
                float dlb = inp[base + 5 * cs];
                float xm  = xmean[(grow * Tt + t) * (long)Dd + j];
                float dz  = __expf(-fmaxf(fmaf(dl,  wzd[j], bzs[j]),  0.0f));
                float dzp = __expf(-fmaxf(fmaf(dlb, wzp[j], bzps[j]), 0.0f));
                sm[OFF_U + row * U_STR + j]       = mk * x + (1.0f - mk) * (dz  * xl  + (1.0f - dz)  * xm);
                sm[OFF_U + row * U_STR + 128 + j] = mk * x + (1.0f - mk) * (dzp * xlb + (1.0f - dzp) * xm);
            }
        }
        cluster_sync_();   // S_a: z/zp local + prev x_i pushes visible

        // ---------- Phase B: ls slice (8 m's), k split in halves ----------
        {
            int ks = tid >> 7, oi = tid & 127, m = oi & 7, row = oi >> 3;
            const u64* __restrict__ w2 =
                reinterpret_cast<const u64*>(g_Wq2 + ((int)rank * 8 + m) * 192 + ks * 96);
            const float* urow = sm + OFF_U + row * U_STR + ks * 192;
            u64 a0 = 0ull, a1 = 0ull;
#pragma unroll 8
            for (int p = 0; p < 96; p += 2) {
                fma2(a0, w2[p],     *reinterpret_cast<const u64*>(urow + 2 * p));
                fma2(a1, w2[p + 1], *reinterpret_cast<const u64*>(urow + 2 * p + 2));
            }
            float x0, x1, y0, y1; unpack2(a0, x0, x1); unpack2(a1, y0, y1);
            sm[OFF_PB + oi * 2 + ks] = (x0 + x1) + (y0 + y1);
        }
        __syncthreads();
        if (tid < 128) {
            int m = tid & 7, row = tid >> 3;
            float v = bq[(int)rank * 8 + m] + sm[OFF_PB + tid * 2] + sm[OFF_PB + tid * 2 + 1];
            uint32_t off = (uint32_t)(OFF_LS + row * LS_STR + (int)rank * 8 + m) * 4u;
#pragma unroll
            for (int r = 0; r < CLS; r++) stc(pb[r] + off, v);
        }
        cluster_sync_();   // S_b: ls visible everywhere

        // ---------- Phase C: gates for own 32 h's, rows (rg, rg+8) ----------
        {
            const int hl = tid >> 3, rg = tid & 7;
            const int r0 = rg, r1 = rg + 8;
            const ulonglong2* __restrict__ wb = reinterpret_cast<const ulonglong2*>(sm) + hl;
            u64 aif0 = bias_if, aoc0 = bias_oc, aif1 = bias_if, aoc1 = bias_oc;
            {
                const float* p0 = sm + OFF_LS + r0 * LS_STR;
                const float* p1 = sm + OFF_LS + r1 * LS_STR;
#pragma unroll 4
                for (int k0 = 0; k0 < 64; k0 += 4) CBODY(p0 + k0, p1 + k0, wb + k0 * 32);
            }
            {
                const float* p0 = sm + OFF_H + prv * H_BUF + r0 * H_STR;
                const float* p1 = sm + OFF_H + prv * H_BUF + r1 * H_STR;
#pragma unroll 4
                for (int k0 = 0; k0 < 256; k0 += 4) CBODY(p0 + k0, p1 + k0, wb + (64 + k0) * 32);
            }
            float ai, afv, ao, ac, h0, h1;
            unpack2(aif0, ai, afv); unpack2(aoc0, ao, ac);
            {
                float ig = fast_sigmoid(ai), fg = fast_sigmoid(afv);
                float og = fast_sigmoid(ao), ct = fast_tanh(ac);
                c_reg0 = fg * c_reg0 + ig * ct;
                h0 = og * fast_tanh(c_reg0);
            }
            unpack2(aif1, ai, afv); unpack2(aoc1, ao, ac);
            {
                float ig = fast_sigmoid(ai), fg = fast_sigmoid(afv);
                float og = fast_sigmoid(ao), ct = fast_tanh(ac);
                c_reg1 = fg * c_reg1 + ig * ct;
                h1 = og * fast_tanh(c_reg1);
            }
            uint32_t off0 = (uint32_t)(OFF_H + cur * H_BUF + r0 * H_STR + hg) * 4u;
            uint32_t off1 = (uint32_t)(OFF_H + cur * H_BUF + r1 * H_STR + hg) * 4u;
#pragma unroll
            for (int r = 0; r < CLS; r++) { stc(pb[r] + off0, h0); stc(pb[r] + off1, h1); }
        }
        cluster_sync_();   // S_c: h_t visible everywhere

        // ---------- Phase E: out slice (16 o's) for all rows; feeds x_i_{t+1} ----------
        {
            int row = tid >> 4, ol = tid & 15;
            int o = (int)rank * 16 + ol;
            const u64* __restrict__ w2 = reinterpret_cast<const u64*>(g_Wfc2 + o * 128);
            const float* hr = sm + OFF_H + cur * H_BUF + row * H_STR;
            u64 a0 = 0ull, a1 = 0ull;
#pragma unroll 8
            for (int hp = 0; hp < 128; hp += 2) {
                fma2(a0, w2[hp],     *reinterpret_cast<const u64*>(hr + 2 * hp));
                fma2(a1, w2[hp + 1], *reinterpret_cast<const u64*>(hr + 2 * hp + 2));
            }
            float x0, x1, y0, y1; unpack2(a0, x0, x1); unpack2(a1, y0, y1);
            float v = sm[OFF_MISC + 512 + o] + (x0 + x1) + (y0 + y1);
            out[((long)(b0 + row) * Tt + t) * 128 + o] = v;
            uint32_t off = (uint32_t)(OFF_U + row * U_STR + 256 + o) * 4u;
#pragma unroll
            for (int r = 0; r < CLS; r++) stc(pb[r] + off, v);
        }
        // next iteration: Phase A writes u[0:256) (disjoint), S_a covers x_i visibility
    }
    cluster_sync_();   // no CTA exits while peers may still push into its SMEM
}

extern "C" void kernel_launch(void* const* d_in, const int* in_sizes, int n_in,
                              void* d_out, int out_size)
{
    const float* inp   = (const float*)d_in[0];
    const float* xmean = (const float*)d_in[1];
    const float* Wz    = (const float*)d_in[2];
    const float* bz    = (const float*)d_in[3];
    const float* Wzp   = (const float*)d_in[4];
    const float* bzp   = (const float*)d_in[5];
    const float* Wq    = (const float*)d_in[6];
    const float* bq    = (const float*)d_in[7];
    const float* Wi    = (const float*)d_in[8];
    const float* bi    = (const float*)d_in[9];
    const float* Wf    = (const float*)d_in[10];
    const float* bf    = (const float*)d_in[11];
    const float* Wo    = (const float*)d_in[12];
    const float* bo    = (const float*)d_in[13];
    const float* Wc    = (const float*)d_in[14];
    const float* bc    = (const float*)d_in[15];
    const float* Wfc   = (const float*)d_in[16];
    const float* bfc   = (const float*)d_in[17];
    float* out = (float*)d_out;

    cudaFuncSetAttribute(lgnet_kernel, cudaFuncAttributeMaxDynamicSharedMemorySize, SMEM_BYTES);

    prep_kernel<<<320, 256>>>(Wz, Wzp, Wq, Wi, Wf, Wo, Wc, Wfc);
    lgnet_kernel<<<NBLK, NTHR, SMEM_BYTES>>>(inp, xmean, bz, bzp, bq, bi, bf, bo, bc, bfc, out);
}

// round 5
// speedup vs baseline: 4.0926x; 4.0926x over previous
#include <cuda_runtime.h>
#include <cstdint>

#define Bsz 256
#define Tt  200
#define Dd  128
#define Hh  256
#define Oo  128
#define Mm  64
#define RPB 4
#define NBLK (Bsz/RPB)     // 64 scan CTAs
#define NTHR 256
#define KPAD 272           // 256 k's + 16 pad for prefetch
#define RES_K 48           // k-slices of Bh resident in SMEM
#define BT  (Bsz*Tt)       // 51200
#define RPP 16             // bt-rows per G-precompute CTA
#define EROWS 32           // bt-rows per epilogue CTA

typedef unsigned long long u64;

// ---------------- device globals (no allocs allowed) ----------------
__device__ __align__(16) float4 g_A4 [KPAD * 256];   // [k][h] = (Ai,Af,Ao,Ac)[h][k], k indexes [z|zp]
__device__ __align__(16) float4 g_Bh4[KPAD * 256];   // [k][h] = (Bi,Bf,Bo,Bc)[h][k], k indexes h_prev
__device__ __align__(16) float4 g_bias4[256];        // folded gate biases
__device__ float  g_Wqh[64 * 256];                   // Wq_h = Wq[:,256:384] @ Wfc   [m][hc]
__device__ float  g_bqe[64];                         // bq + Wq[:,256:] @ bfc
__device__ __align__(8) float2 g_WfcT2[128 * 128];   // [hp][o] = (Wfc[o][2hp], Wfc[o][2hp+1])
__device__ float  g_wzd[128], g_wzpd[128];
__device__ __align__(16) float4 g_G4[(long)BT * 256];// 200 MB: precomputed A@[z,zp]+bias
__device__ float  g_H [(long)BT * 256];              // 50 MB: h_t for the epilogue

// ---------------- helpers ----------------
__device__ __forceinline__ float fast_sigmoid(float x) { return 1.0f / (1.0f + __expf(-x)); }
__device__ __forceinline__ float fast_tanh(float x)    { return 1.0f - 2.0f / (__expf(2.0f * x) + 1.0f); }
__device__ __forceinline__ u64 pack2(float lo, float hi) {
    u64 r; asm("mov.b64 %0, {%1, %2};" : "=l"(r) : "f"(lo), "f"(hi)); return r;
}
__device__ __forceinline__ u64 dup2(float v) {
    u64 r; asm("mov.b64 %0, {%1, %1};" : "=l"(r) : "f"(v)); return r;
}
__device__ __forceinline__ void unpack2(u64 v, float& lo, float& hi) {
    asm("mov.b64 {%0, %1}, %2;" : "=f"(lo), "=f"(hi) : "l"(v));
}
__device__ __forceinline__ void fma2(u64& d, u64 a, u64 b) {
    asm("fma.rn.f32x2 %0, %1, %2, %0;" : "+l"(d) : "l"(a), "l"(b));
}
// L2-cached (L1-bypassing) 16B load as two packed u64 lanes
__device__ __forceinline__ ulonglong2 ldcg_v2(const ulonglong2* p) {
    ulonglong2 v;
    asm("ld.global.cg.v2.b64 {%0, %1}, [%2];" : "=l"(v.x), "=l"(v.y) : "l"(p));
    return v;
}

// ================= prep1: Wq_h = Wq_xi @ Wfc ; bq_eff =================
__global__ void prep1_kernel(const float* __restrict__ Wq, const float* __restrict__ Wfc,
                             const float* __restrict__ bq, const float* __restrict__ bfc)
{
    int m = blockIdx.x, hc = threadIdx.x;     // grid 64, block 256
    float s = 0.0f;
    for (int o = 0; o < 128; o++)
        s = fmaf(Wq[m * 384 + 256 + o], Wfc[o * 256 + hc], s);
    g_Wqh[m * 256 + hc] = s;
    if (hc == 0) {
        float s2 = bq[m];
        for (int o = 0; o < 128; o++)
            s2 = fmaf(Wq[m * 384 + 256 + o], bfc[o], s2);
        g_bqe[m] = s2;
    }
}

// ================= prep2: fold A, Bh, biases; misc layouts =================
__global__ void prep2_kernel(const float* __restrict__ Wz, const float* __restrict__ Wzp,
                             const float* __restrict__ Wq,
                             const float* __restrict__ Wi, const float* __restrict__ bi,
                             const float* __restrict__ Wf, const float* __restrict__ bf,
                             const float* __restrict__ Wo, const float* __restrict__ bo,
                             const float* __restrict__ Wc, const float* __restrict__ bc,
                             const float* __restrict__ Wfc)
{
    int k = blockIdx.x, h = threadIdx.x;      // grid KPAD(272), block 256
    if (k < 256) {
        float4 a = make_float4(0.f, 0.f, 0.f, 0.f);
        float4 bh;
        bh.x = Wi[h * 320 + 64 + k];
        bh.y = Wf[h * 320 + 64 + k];
        bh.z = Wo[h * 320 + 64 + k];
        bh.w = Wc[h * 320 + 64 + k];
        for (int m = 0; m < 64; m++) {
            float q  = Wq[m * 384 + k];
            float qh = g_Wqh[m * 256 + k];
            float wi = Wi[h * 320 + m], wf = Wf[h * 320 + m];
            float wo = Wo[h * 320 + m], wc = Wc[h * 320 + m];
            a.x = fmaf(wi, q, a.x);  a.y = fmaf(wf, q, a.y);
            a.z = fmaf(wo, q, a.z);  a.w = fmaf(wc, q, a.w);
            bh.x = fmaf(wi, qh, bh.x); bh.y = fmaf(wf, qh, bh.y);
            bh.z = fmaf(wo, qh, bh.z); bh.w = fmaf(wc, qh, bh.w);
        }
        g_A4 [k * 256 + h] = a;
        g_Bh4[k * 256 + h] = bh;
    } else {
        float4 zz = make_float4(0.f, 0.f, 0.f, 0.f);
        g_A4 [k * 256 + h] = zz;
        g_Bh4[k * 256 + h] = zz;
    }
    if (k == 0) {
        float4 b4 = make_float4(bi[h], bf[h], bo[h], bc[h]);
        for (int m = 0; m < 64; m++) {
            float e = g_bqe[m];
            b4.x = fmaf(Wi[h * 320 + m], e, b4.x);
            b4.y = fmaf(Wf[h * 320 + m], e, b4.y);
            b4.z = fmaf(Wo[h * 320 + m], e, b4.z);
            b4.w = fmaf(Wc[h * 320 + m], e, b4.w);
        }
        g_bias4[h] = b4;
    }
    if (k == 1 && h < 128) {
        g_wzd[h]  = Wz[h * 128 + h];
        g_wzpd[h] = Wzp[h * 128 + h];
    }
    if (k < 128 && h < 128)   // WfcT2[hp=k][o=h]
        g_WfcT2[k * 128 + h] = make_float2(Wfc[h * 256 + 2 * k], Wfc[h * 256 + 2 * k + 1]);
}

// ================= G precompute: G = A @ [z,zp] + bias, all (b,t) in parallel ==========
__global__ __launch_bounds__(NTHR) void gpre_kernel(
    const float* __restrict__ inp, const float* __restrict__ xmean,
    const float* __restrict__ bz,  const float* __restrict__ bzp)
{
    __shared__ __align__(16) u64 u2dup[RPP * 256];   // 32 KB, (v,v) duplicated
    __shared__ float s_wzd[128], s_bz[128], s_wzpd[128], s_bzp[128];

    const int tid = threadIdx.x;
    const int bt0 = blockIdx.x * RPP;                 // grid = BT/RPP = 3200

    if (tid < 128) {
        s_wzd[tid] = g_wzd[tid];   s_bz[tid]  = bz[tid];
        s_wzpd[tid] = g_wzpd[tid]; s_bzp[tid] = bzp[tid];
    }
    __syncthreads();

    // ---- Phase A: z, zp for RPP rows ----
    const long cs = (long)Tt * Dd;
    for (int e = tid; e < RPP * 128; e += NTHR) {
        int row = e >> 7, j = e & 127;
        int bt = bt0 + row, b = bt / Tt, t = bt - b * Tt;
        long base = ((long)b * 6 * Tt + t) * (long)Dd + j;
        float x   = inp[base];
        float xl  = inp[base + 1 * cs];
        float mk  = inp[base + 2 * cs];
        float dl  = inp[base + 3 * cs];
        float xlb = inp[base + 4 * cs];
        float dlb = inp[base + 5 * cs];
        float xm  = xmean[((long)b * Tt + t) * (long)Dd + j];
        float dz  = __expf(-fmaxf(fmaf(dl,  s_wzd[j],  s_bz[j]),  0.0f));
        float dzp = __expf(-fmaxf(fmaf(dlb, s_wzpd[j], s_bzp[j]), 0.0f));
        float z   = mk * x + (1.0f - mk) * (dz  * xl  + (1.0f - dz)  * xm);
        float zp  = mk * x + (1.0f - mk) * (dzp * xlb + (1.0f - dzp) * xm);
        u2dup[row * 256 + j]       = dup2(z);
        u2dup[row * 256 + 128 + j] = dup2(zp);
    }
    __syncthreads();

    // ---- GEMM: acc(h=tid) over 256 k, 16 rows, gates packed (i,f)/(o,c) ----
    u64 aif[RPP], aoc[RPP];
    {
        float4 b4 = g_bias4[tid];
#pragma unroll
        for (int r = 0; r < RPP; r++) { aif[r] = pack2(b4.x, b4.y); aoc[r] = pack2(b4.z, b4.w); }
    }
    const ulonglong2* __restrict__ wg = reinterpret_cast<const ulonglong2*>(g_A4) + tid;
    ulonglong2 wb[8];
#pragma unroll
    for (int i = 0; i < 8; i++) wb[i] = ldcg_v2(wg + i * 256);
#pragma unroll 1
    for (int k0 = 0; k0 < 256; k0 += 8) {
#pragma unroll
        for (int i = 0; i < 8; i += 2) {
            ulonglong2 w0 = wb[i], w1 = wb[i + 1];
            wb[i]     = ldcg_v2(wg + (k0 + 8 + i) * 256);
            wb[i + 1] = ldcg_v2(wg + (k0 + 9 + i) * 256);
#pragma unroll
            for (int r = 0; r < RPP; r++) {
                ulonglong2 hh = *reinterpret_cast<const ulonglong2*>(&u2dup[r * 256 + k0 + i]);
                fma2(aif[r], w0.x, hh.x); fma2(aoc[r], w0.y, hh.x);
                fma2(aif[r], w1.x, hh.y); fma2(aoc[r], w1.y, hh.y);
            }
        }
    }
#pragma unroll
    for (int r = 0; r < RPP; r++) {
        float gi, gf, go, gc;
        unpack2(aif[r], gi, gf); unpack2(aoc[r], go, gc);
        g_G4[(long)(bt0 + r) * 256 + tid] = make_float4(gi, gf, go, gc);
    }
}

// ================= scan: h_t = lstm(G_t + Bh @ h_{t-1}) =================
__global__ __launch_bounds__(NTHR) void scan_kernel()
{
    extern __shared__ __align__(16) char smraw[];
    ulonglong2* resW = reinterpret_cast<ulonglong2*>(smraw);            // [RES_K][256]
    u64* hdup = reinterpret_cast<u64*>(smraw + RES_K * 256 * 16);       // [2][RPB][256]

    const int tid = threadIdx.x;
    const int b0  = blockIdx.x * RPB;

    // resident Bh slice (k < RES_K) -> SMEM
    {
        const ulonglong2* src = reinterpret_cast<const ulonglong2*>(g_Bh4);
        for (int i = tid; i < RES_K * 256; i += NTHR) resW[i] = src[i];
    }
    for (int i = tid; i < 2 * RPB * 256; i += NTHR) hdup[i] = 0ull;     // h0 = 0

    float c_reg[RPB];
#pragma unroll
    for (int r = 0; r < RPB; r++) c_reg[r] = 0.0f;

    const float4* __restrict__ G4 = g_G4;
    float4 gv[RPB], gvn[RPB];
#pragma unroll
    for (int r = 0; r < RPB; r++) gv[r] = G4[(long)(b0 + r) * Tt * 256 + tid];
    __syncthreads();

    const ulonglong2* __restrict__ wg = reinterpret_cast<const ulonglong2*>(g_Bh4) + tid;

    for (int t = 0; t < Tt; t++) {
        const int cur = t & 1, prv = cur ^ 1;
        const u64* hp = hdup + prv * RPB * 256;

        // issue next-step G loads early (deep latency hiding)
        int tn = (t + 1 < Tt) ? t + 1 : t;
#pragma unroll
        for (int r = 0; r < RPB; r++)
            gvn[r] = G4[((long)(b0 + r) * Tt + tn) * 256 + tid];

        u64 aif[RPB], aoc[RPB];
#pragma unroll
        for (int r = 0; r < RPB; r++) {
            aif[r] = pack2(gv[r].x, gv[r].y);
            aoc[r] = pack2(gv[r].z, gv[r].w);
        }

        // prefetch streamed weights
        ulonglong2 wb[8];
#pragma unroll
        for (int i = 0; i < 8; i++) wb[i] = ldcg_v2(wg + (RES_K + i) * 256);

        // ---- resident part: k in [0, RES_K) ----
        const ulonglong2* rw = resW + tid;
#pragma unroll 4
        for (int k = 0; k < RES_K; k += 2) {
            ulonglong2 w0 = rw[k * 256], w1 = rw[(k + 1) * 256];
#pragma unroll
            for (int r = 0; r < RPB; r++) {
                ulonglong2 hh = *reinterpret_cast<const ulonglong2*>(&hp[r * 256 + k]);
                fma2(aif[r], w0.x, hh.x); fma2(aoc[r], w0.y, hh.x);
                fma2(aif[r], w1.x, hh.y); fma2(aoc[r], w1.y, hh.y);
            }
        }

        // ---- streamed part: k in [RES_K, 256), depth-8 pipeline ----
#pragma unroll 1
        for (int k0 = RES_K; k0 < 256; k0 += 8) {
#pragma unroll
            for (int i = 0; i < 8; i += 2) {
                ulonglong2 w0 = wb[i], w1 = wb[i + 1];
                wb[i]     = ldcg_v2(wg + (k0 + 8 + i) * 256);   // padded to KPAD
                wb[i + 1] = ldcg_v2(wg + (k0 + 9 + i) * 256);
#pragma unroll
                for (int r = 0; r < RPB; r++) {
                    ulonglong2 hh = *reinterpret_cast<const ulonglong2*>(&hp[r * 256 + k0 + i]);
                    fma2(aif[r], w0.x, hh.x); fma2(aoc[r], w0.y, hh.x);
                    fma2(aif[r], w1.x, hh.y); fma2(aoc[r], w1.y, hh.y);
                }
            }
        }

        // ---- activations, state update, publish h ----
        u64* hc = hdup + cur * RPB * 256;
#pragma unroll
        for (int r = 0; r < RPB; r++) {
            float ai, afv, ao, ac;
            unpack2(aif[r], ai, afv); unpack2(aoc[r], ao, ac);
            float ig = fast_sigmoid(ai), fg = fast_sigmoid(afv);
            float og = fast_sigmoid(ao), ct = fast_tanh(ac);
            c_reg[r] = fg * c_reg[r] + ig * ct;
            float hv = og * fast_tanh(c_reg[r]);
            hc[r * 256 + tid] = dup2(hv);
            g_H[((long)(b0 + r) * Tt + t) * 256 + tid] = hv;
            gv[r] = gvn[r];
        }
        __syncthreads();
    }
}

// ================= epilogue: out = H @ Wfc^T + bfc (fully parallel) =================
__global__ __launch_bounds__(NTHR) void epi_kernel(const float* __restrict__ bfc,
                                                   float* __restrict__ out)
{
    __shared__ __align__(16) float hs[EROWS * 256];   // 32 KB
    const int tid = threadIdx.x;
    const int bt0 = blockIdx.x * EROWS;               // grid = BT/EROWS = 1600

    for (int e = tid; e < EROWS * 256; e += NTHR)
        hs[e] = g_H[(long)bt0 * 256 + e];
    __syncthreads();

    const int o  = tid & 127;
    const int rb = (tid >> 7) * 16;                   // rows rb .. rb+15
    u64 acc[16];
#pragma unroll
    for (int r = 0; r < 16; r++) acc[r] = 0ull;

    const u64* __restrict__ w2 = reinterpret_cast<const u64*>(g_WfcT2) + o;
#pragma unroll 4
    for (int hpi = 0; hpi < 128; hpi++) {
        u64 w = w2[hpi * 128];
#pragma unroll
        for (int r = 0; r < 16; r++)
            fma2(acc[r], w, *reinterpret_cast<const u64*>(&hs[(rb + r) * 256 + 2 * hpi]));
    }
    const float bo_ = bfc[o];
#pragma unroll
    for (int r = 0; r < 16; r++) {
        float x0, x1; unpack2(acc[r], x0, x1);
        out[(long)(bt0 + rb + r) * Oo + o] = bo_ + x0 + x1;
    }
}

// ================= launch =================
#define SCAN_SMEM (RES_K*256*16 + 2*RPB*256*8)

extern "C" void kernel_launch(void* const* d_in, const int* in_sizes, int n_in,
                              void* d_out, int out_size)
{
    const float* inp   = (const float*)d_in[0];
    const float* xmean = (const float*)d_in[1];
    const float* Wz    = (const float*)d_in[2];
    const float* bz    = (const float*)d_in[3];
    const float* Wzp   = (const float*)d_in[4];
    const float* bzp   = (const float*)d_in[5];
    const float* Wq    = (const float*)d_in[6];
    const float* bq    = (const float*)d_in[7];
    const float* Wi    = (const float*)d_in[8];
    const float* bi    = (const float*)d_in[9];
    const float* Wf    = (const float*)d_in[10];
    const float* bf    = (const float*)d_in[11];
    const float* Wo    = (const float*)d_in[12];
    const float* bo    = (const float*)d_in[13];
    const float* Wc    = (const float*)d_in[14];
    const float* bc    = (const float*)d_in[15];
    const float* Wfc   = (const float*)d_in[16];
    const float* bfc   = (const float*)d_in[17];
    float* out = (float*)d_out;

    static int attr_done = 0;
    if (!attr_done) {
        cudaFuncSetAttribute(scan_kernel, cudaFuncAttributeMaxDynamicSharedMemorySize, SCAN_SMEM);
        attr_done = 1;
    }

    prep1_kernel<<<64, 256>>>(Wq, Wfc, bq, bfc);
    prep2_kernel<<<KPAD, 256>>>(Wz, Wzp, Wq, Wi, bi, Wf, bf, Wo, bo, Wc, bc, Wfc);
    gpre_kernel<<<BT / RPP, NTHR>>>(inp, xmean, bz, bzp);
    scan_kernel<<<NBLK, NTHR, SCAN_SMEM>>>();
    epi_kernel<<<BT / EROWS, NTHR>>>(bfc, out);
}

// round 6
// speedup vs baseline: 4.3315x; 1.0584x over previous
#include <cuda_runtime.h>
#include <cstdint>

#define Bsz 256
#define Tt  200
#define Dd  128
#define Hh  256
#define Oo  128
#define Mm  64
#define RPB 4
#define NBLK (Bsz/RPB)     // 64 scan CTAs
#define NTHR 256
#define SCTH 512           // scan threads (2 k-groups of 256)
#define KPAD 272           // 256 k's + 16 pad for prefetch
#define RES_K 48           // k-slices of Bh resident in SMEM (24 per k-group)
#define RES_H 24           // per group
#define BT  (Bsz*Tt)       // 51200
#define RPP 16             // bt-rows per G-precompute CTA
#define EROWS 32           // bt-rows per epilogue CTA

typedef unsigned long long u64;

// ---------------- device globals (no allocs allowed) ----------------
__device__ __align__(16) float4 g_A4 [KPAD * 256];   // [k][h] = (Ai,Af,Ao,Ac)[h][k], k indexes [z|zp]
__device__ __align__(16) float4 g_Bh4[KPAD * 256];   // [k][h] = (Bi,Bf,Bo,Bc)[h][k], k indexes h_prev
__device__ __align__(16) float4 g_bias4[256];        // folded gate biases
__device__ float  g_Wqh[64 * 256];                   // Wq_h = Wq[:,256:384] @ Wfc   [m][hc]
__device__ float  g_bqe[64];                         // bq + Wq[:,256:] @ bfc
__device__ __align__(8) float2 g_WfcT2[128 * 128];   // [hp][o] = (Wfc[o][2hp], Wfc[o][2hp+1])
__device__ float  g_wzd[128], g_wzpd[128];
__device__ __align__(16) float4 g_G4[(long)BT * 256];// 200 MB: precomputed A@[z,zp]+bias
__device__ float  g_H [(long)BT * 256];              // 50 MB: h_t for the epilogue

// ---------------- helpers ----------------
__device__ __forceinline__ float fast_sigmoid(float x) { return 1.0f / (1.0f + __expf(-x)); }
__device__ __forceinline__ float fast_tanh(float x)    { return 1.0f - 2.0f / (__expf(2.0f * x) + 1.0f); }
__device__ __forceinline__ u64 pack2(float lo, float hi) {
    u64 r; asm("mov.b64 %0, {%1, %2};" : "=l"(r) : "f"(lo), "f"(hi)); return r;
}
__device__ __forceinline__ u64 dup2(float v) {
    u64 r; asm("mov.b64 %0, {%1, %1};" : "=l"(r) : "f"(v)); return r;
}
__device__ __forceinline__ void unpack2(u64 v, float& lo, float& hi) {
    asm("mov.b64 {%0, %1}, %2;" : "=f"(lo), "=f"(hi) : "l"(v));
}
__device__ __forceinline__ void fma2(u64& d, u64 a, u64 b) {
    asm("fma.rn.f32x2 %0, %1, %2, %0;" : "+l"(d) : "l"(a), "l"(b));
}
__device__ __forceinline__ u64 add2(u64 a, u64 b) {
    u64 r; asm("add.rn.f32x2 %0, %1, %2;" : "=l"(r) : "l"(a), "l"(b)); return r;
}
// L2-cached (L1-bypassing) 16B load as two packed u64 lanes
__device__ __forceinline__ ulonglong2 ldcg_v2(const ulonglong2* p) {
    ulonglong2 v;
    asm("ld.global.cg.v2.b64 {%0, %1}, [%2];" : "=l"(v.x), "=l"(v.y) : "l"(p));
    return v;
}

// ================= prep1: Wq_h = Wq_xi @ Wfc ; bq_eff =================
__global__ void prep1_kernel(const float* __restrict__ Wq, const float* __restrict__ Wfc,
                             const float* __restrict__ bq, const float* __restrict__ bfc)
{
    int m = blockIdx.x, hc = threadIdx.x;     // grid 64, block 256
    float s = 0.0f;
    for (int o = 0; o < 128; o++)
        s = fmaf(Wq[m * 384 + 256 + o], Wfc[o * 256 + hc], s);
    g_Wqh[m * 256 + hc] = s;
    if (hc == 0) {
        float s2 = bq[m];
        for (int o = 0; o < 128; o++)
            s2 = fmaf(Wq[m * 384 + 256 + o], bfc[o], s2);
        g_bqe[m] = s2;
    }
}

// ================= prep2: fold A, Bh, biases; misc layouts =================
__global__ void prep2_kernel(const float* __restrict__ Wz, const float* __restrict__ Wzp,
                             const float* __restrict__ Wq,
                             const float* __restrict__ Wi, const float* __restrict__ bi,
                             const float* __restrict__ Wf, const float* __restrict__ bf,
                             const float* __restrict__ Wo, const float* __restrict__ bo,
                             const float* __restrict__ Wc, const float* __restrict__ bc,
                             const float* __restrict__ Wfc)
{
    int k = blockIdx.x, h = threadIdx.x;      // grid KPAD(272), block 256
    if (k < 256) {
        float4 a = make_float4(0.f, 0.f, 0.f, 0.f);
        float4 bh;
        bh.x = Wi[h * 320 + 64 + k];
        bh.y = Wf[h * 320 + 64 + k];
        bh.z = Wo[h * 320 + 64 + k];
        bh.w = Wc[h * 320 + 64 + k];
        for (int m = 0; m < 64; m++) {
            float q  = Wq[m * 384 + k];
            float qh = g_Wqh[m * 256 + k];
            float wi = Wi[h * 320 + m], wf = Wf[h * 320 + m];
            float wo = Wo[h * 320 + m], wc = Wc[h * 320 + m];
            a.x = fmaf(wi, q, a.x);  a.y = fmaf(wf, q, a.y);
            a.z = fmaf(wo, q, a.z);  a.w = fmaf(wc, q, a.w);
            bh.x = fmaf(wi, qh, bh.x); bh.y = fmaf(wf, qh, bh.y);
            bh.z = fmaf(wo, qh, bh.z); bh.w = fmaf(wc, qh, bh.w);
        }
        g_A4 [k * 256 + h] = a;
        g_Bh4[k * 256 + h] = bh;
    } else {
        float4 zz = make_float4(0.f, 0.f, 0.f, 0.f);
        g_A4 [k * 256 + h] = zz;
        g_Bh4[k * 256 + h] = zz;
    }
    if (k == 0) {
        float4 b4 = make_float4(bi[h], bf[h], bo[h], bc[h]);
        for (int m = 0; m < 64; m++) {
            float e = g_bqe[m];
            b4.x = fmaf(Wi[h * 320 + m], e, b4.x);
            b4.y = fmaf(Wf[h * 320 + m], e, b4.y);
            b4.z = fmaf(Wo[h * 320 + m], e, b4.z);
            b4.w = fmaf(Wc[h * 320 + m], e, b4.w);
        }
        g_bias4[h] = b4;
    }
    if (k == 1 && h < 128) {
        g_wzd[h]  = Wz[h * 128 + h];
        g_wzpd[h] = Wzp[h * 128 + h];
    }
    if (k < 128 && h < 128)   // WfcT2[hp=k][o=h]
        g_WfcT2[k * 128 + h] = make_float2(Wfc[h * 256 + 2 * k], Wfc[h * 256 + 2 * k + 1]);
}

// ================= G precompute: G = A @ [z,zp] + bias, all (b,t) in parallel ==========
__global__ __launch_bounds__(NTHR) void gpre_kernel(
    const float* __restrict__ inp, const float* __restrict__ xmean,
    const float* __restrict__ bz,  const float* __restrict__ bzp)
{
    __shared__ __align__(16) u64 u2dup[RPP * 256];   // 32 KB, (v,v) duplicated
    __shared__ float s_wzd[128], s_bz[128], s_wzpd[128], s_bzp[128];

    const int tid = threadIdx.x;
    const int bt0 = blockIdx.x * RPP;                 // grid = BT/RPP = 3200

    if (tid < 128) {
        s_wzd[tid] = g_wzd[tid];   s_bz[tid]  = bz[tid];
        s_wzpd[tid] = g_wzpd[tid]; s_bzp[tid] = bzp[tid];
    }
    __syncthreads();

    // ---- Phase A: z, zp for RPP rows ----
    const long cs = (long)Tt * Dd;
    for (int e = tid; e < RPP * 128; e += NTHR) {
        int row = e >> 7, j = e & 127;
        int bt = bt0 + row, b = bt / Tt, t = bt - b * Tt;
        long base = ((long)b * 6 * Tt + t) * (long)Dd + j;
        float x   = inp[base];
        float xl  = inp[base + 1 * cs];
        float mk  = inp[base + 2 * cs];
        float dl  = inp[base + 3 * cs];
        float xlb = inp[base + 4 * cs];
        float dlb = inp[base + 5 * cs];
        float xm  = xmean[((long)b * Tt + t) * (long)Dd + j];
        float dz  = __expf(-fmaxf(fmaf(dl,  s_wzd[j],  s_bz[j]),  0.0f));
        float dzp = __expf(-fmaxf(fmaf(dlb, s_wzpd[j], s_bzp[j]), 0.0f));
        float z   = mk * x + (1.0f - mk) * (dz  * xl  + (1.0f - dz)  * xm);
        float zp  = mk * x + (1.0f - mk) * (dzp * xlb + (1.0f - dzp) * xm);
        u2dup[row * 256 + j]       = dup2(z);
        u2dup[row * 256 + 128 + j] = dup2(zp);
    }
    __syncthreads();

    // ---- GEMM: acc(h=tid) over 256 k, 16 rows, gates packed (i,f)/(o,c) ----
    u64 aif[RPP], aoc[RPP];
    {
        float4 b4 = g_bias4[tid];
#pragma unroll
        for (int r = 0; r < RPP; r++) { aif[r] = pack2(b4.x, b4.y); aoc[r] = pack2(b4.z, b4.w); }
    }
    const ulonglong2* __restrict__ wg = reinterpret_cast<const ulonglong2*>(g_A4) + tid;
    ulonglong2 wb[8];
#pragma unroll
    for (int i = 0; i < 8; i++) wb[i] = ldcg_v2(wg + i * 256);
#pragma unroll 1
    for (int k0 = 0; k0 < 256; k0 += 8) {
#pragma unroll
        for (int i = 0; i < 8; i += 2) {
            ulonglong2 w0 = wb[i], w1 = wb[i + 1];
            wb[i]     = ldcg_v2(wg + (k0 + 8 + i) * 256);
            wb[i + 1] = ldcg_v2(wg + (k0 + 9 + i) * 256);
#pragma unroll
            for (int r = 0; r < RPP; r++) {
                ulonglong2 hh = *reinterpret_cast<const ulonglong2*>(&u2dup[r * 256 + k0 + i]);
                fma2(aif[r], w0.x, hh.x); fma2(aoc[r], w0.y, hh.x);
                fma2(aif[r], w1.x, hh.y); fma2(aoc[r], w1.y, hh.y);
            }
        }
    }
#pragma unroll
    for (int r = 0; r < RPP; r++) {
        float gi, gf, go, gc;
        unpack2(aif[r], gi, gf); unpack2(aoc[r], go, gc);
        g_G4[(long)(bt0 + r) * 256 + tid] = make_float4(gi, gf, go, gc);
    }
}

// ================= scan: h_t = lstm(G_t + Bh @ h_{t-1}) =================
// 512 threads: k-group ks = tid>>8 handles k in [ks*128, ks*128+128) for h = tid&255.
// Group 1 writes packed partials to SMEM; group 0 reduces + activations + h publish.
__global__ __launch_bounds__(SCTH) void scan_kernel()
{
    extern __shared__ __align__(16) char smraw[];
    ulonglong2* resW = reinterpret_cast<ulonglong2*>(smraw);              // [RES_K][256]
    u64* hdup = reinterpret_cast<u64*>(smraw + RES_K * 256 * 16);         // [2][RPB][256]
    u64* part = reinterpret_cast<u64*>(smraw + RES_K * 256 * 16 + 2 * RPB * 256 * 8); // [RPB][256][2]

    const int tid = threadIdx.x;
    const int ks  = tid >> 8;          // k-group 0/1
    const int hid = tid & 255;         // owned h
    const int b0  = blockIdx.x * RPB;

    // resident Bh slices: group0 <- k[0,24), group1 <- k[128,152)
    for (int i = tid; i < RES_K * 256; i += SCTH) {
        int s = i >> 8, h = i & 255;
        int kg = (s < RES_H) ? s : (128 + s - RES_H);
        resW[i] = reinterpret_cast<const ulonglong2*>(g_Bh4)[kg * 256 + h];
    }
    for (int i = tid; i < 2 * RPB * 256; i += SCTH) hdup[i] = 0ull;       // h0 = 0

    float c_reg[RPB];
#pragma unroll
    for (int r = 0; r < RPB; r++) c_reg[r] = 0.0f;

    const float4* __restrict__ G4 = g_G4;
    float4 gv[RPB], gvn[RPB];
    if (ks == 0) {
#pragma unroll
        for (int r = 0; r < RPB; r++) gv[r] = G4[(long)(b0 + r) * Tt * 256 + hid];
    }
    __syncthreads();

    const int kbase = ks << 7;                           // 0 or 128
    const ulonglong2* __restrict__ wg = reinterpret_cast<const ulonglong2*>(g_Bh4) + hid;
    const ulonglong2* __restrict__ rw = resW + (ks * RES_H) * 256 + hid;

    for (int t = 0; t < Tt; t++) {
        const int cur = t & 1, prv = cur ^ 1;
        const u64* hp = hdup + prv * RPB * 256 + kbase;

        // group 0: prefetch next-step G early
        if (ks == 0) {
            int tn = (t + 1 < Tt) ? t + 1 : t;
#pragma unroll
            for (int r = 0; r < RPB; r++)
                gvn[r] = G4[((long)(b0 + r) * Tt + tn) * 256 + hid];
        }

        u64 aif[RPB], aoc[RPB];
#pragma unroll
        for (int r = 0; r < RPB; r++) {
            if (ks == 0) { aif[r] = pack2(gv[r].x, gv[r].y); aoc[r] = pack2(gv[r].z, gv[r].w); }
            else         { aif[r] = 0ull; aoc[r] = 0ull; }
        }

        // prefetch streamed weights (k = kbase+RES_H .. kbase+127)
        ulonglong2 wb[8];
#pragma unroll
        for (int i = 0; i < 8; i++) wb[i] = ldcg_v2(wg + (kbase + RES_H + i) * 256);

        // ---- resident part: 24 slices ----
#pragma unroll 4
        for (int s = 0; s < RES_H; s += 2) {
            ulonglong2 w0 = rw[s * 256], w1 = rw[(s + 1) * 256];
#pragma unroll
            for (int r = 0; r < RPB; r++) {
                ulonglong2 hh = *reinterpret_cast<const ulonglong2*>(&hp[r * 256 + s]);
                fma2(aif[r], w0.x, hh.x); fma2(aoc[r], w0.y, hh.x);
                fma2(aif[r], w1.x, hh.y); fma2(aoc[r], w1.y, hh.y);
            }
        }

        // ---- streamed part: 104 slices, depth-8 pipeline ----
#pragma unroll 1
        for (int k0 = RES_H; k0 < 128; k0 += 8) {
#pragma unroll
            for (int i = 0; i < 8; i += 2) {
                ulonglong2 w0 = wb[i], w1 = wb[i + 1];
                wb[i]     = ldcg_v2(wg + (kbase + k0 + 8 + i) * 256);   // padded to KPAD
                wb[i + 1] = ldcg_v2(wg + (kbase + k0 + 9 + i) * 256);
#pragma unroll
                for (int r = 0; r < RPB; r++) {
                    ulonglong2 hh = *reinterpret_cast<const ulonglong2*>(&hp[r * 256 + k0 + i]);
                    fma2(aif[r], w0.x, hh.x); fma2(aoc[r], w0.y, hh.x);
                    fma2(aif[r], w1.x, hh.y); fma2(aoc[r], w1.y, hh.y);
                }
            }
        }

        // ---- group 1 deposits partials ----
        if (ks == 1) {
#pragma unroll
            for (int r = 0; r < RPB; r++) {
                ulonglong2 p; p.x = aif[r]; p.y = aoc[r];
                *reinterpret_cast<ulonglong2*>(&part[r * 512 + hid * 2]) = p;
            }
        }
        __syncthreads();

        // ---- group 0: reduce, activations, state update, publish h ----
        if (ks == 0) {
            u64* hc = hdup + cur * RPB * 256;
#pragma unroll
            for (int r = 0; r < RPB; r++) {
                ulonglong2 p = *reinterpret_cast<const ulonglong2*>(&part[r * 512 + hid * 2]);
                u64 tif = add2(aif[r], p.x);
                u64 toc = add2(aoc[r], p.y);
                float ai, afv, ao, ac;
                unpack2(tif, ai, afv); unpack2(toc, ao, ac);
                float ig = fast_sigmoid(ai), fg = fast_sigmoid(afv);
                float og = fast_sigmoid(ao), ct = fast_tanh(ac);
                c_reg[r] = fg * c_reg[r] + ig * ct;
                float hv = og * fast_tanh(c_reg[r]);
                hc[r * 256 + hid] = dup2(hv);
                g_H[((long)(b0 + r) * Tt + t) * 256 + hid] = hv;
                gv[r] = gvn[r];
            }
        }
        __syncthreads();
    }
}

// ================= epilogue: out = H @ Wfc^T + bfc (fully parallel) =================
__global__ __launch_bounds__(NTHR) void epi_kernel(const float* __restrict__ bfc,
                                                   float* __restrict__ out)
{
    __shared__ __align__(16) float hs[EROWS * 256];   // 32 KB
    const int tid = threadIdx.x;
    const int bt0 = blockIdx.x * EROWS;               // grid = BT/EROWS = 1600

    for (int e = tid; e < EROWS * 256; e += NTHR)
        hs[e] = g_H[(long)bt0 * 256 + e];
    __syncthreads();

    const int o  = tid & 127;
    const int rb = (tid >> 7) * 16;                   // rows rb .. rb+15
    u64 acc[16];
#pragma unroll
    for (int r = 0; r < 16; r++) acc[r] = 0ull;

    const u64* __restrict__ w2 = reinterpret_cast<const u64*>(g_WfcT2) + o;
#pragma unroll 4
    for (int hpi = 0; hpi < 128; hpi++) {
        u64 w = w2[hpi * 128];
#pragma unroll
        for (int r = 0; r < 16; r++)
            fma2(acc[r], w, *reinterpret_cast<const u64*>(&hs[(rb + r) * 256 + 2 * hpi]));
    }
    const float bo_ = bfc[o];
#pragma unroll
    for (int r = 0; r < 16; r++) {
        float x0, x1; unpack2(acc[r], x0, x1);
        out[(long)(bt0 + rb + r) * Oo + o] = bo_ + x0 + x1;
    }
}

// ================= launch =================
#define SCAN_SMEM (RES_K*256*16 + 2*RPB*256*8 + RPB*256*2*8)

extern "C" void kernel_launch(void* const* d_in, const int* in_sizes, int n_in,
                              void* d_out, int out_size)
{
    const float* inp   = (const float*)d_in[0];
    const float* xmean = (const float*)d_in[1];
    const float* Wz    = (const float*)d_in[2];
    const float* bz    = (const float*)d_in[3];
    const float* Wzp   = (const float*)d_in[4];
    const float* bzp   = (const float*)d_in[5];
    const float* Wq    = (const float*)d_in[6];
    const float* bq    = (const float*)d_in[7];
    const float* Wi    = (const float*)d_in[8];
    const float* bi    = (const float*)d_in[9];
    const float* Wf    = (const float*)d_in[10];
    const float* bf    = (const float*)d_in[11];
    const float* Wo    = (const float*)d_in[12];
    const float* bo    = (const float*)d_in[13];
    const float* Wc    = (const float*)d_in[14];
    const float* bc    = (const float*)d_in[15];
    const float* Wfc   = (const float*)d_in[16];
    const float* bfc   = (const float*)d_in[17];
    float* out = (float*)d_out;

    static int attr_done = 0;
    if (!attr_done) {
        cudaFuncSetAttribute(scan_kernel, cudaFuncAttributeMaxDynamicSharedMemorySize, SCAN_SMEM);
        attr_done = 1;
    }

    prep1_kernel<<<64, 256>>>(Wq, Wfc, bq, bfc);
    prep2_kernel<<<KPAD, 256>>>(Wz, Wzp, Wq, Wi, bi, Wf, bf, Wo, bo, Wc, bc, Wfc);
    gpre_kernel<<<BT / RPP, NTHR>>>(inp, xmean, bz, bzp);
    scan_kernel<<<NBLK, SCTH, SCAN_SMEM>>>();
    epi_kernel<<<BT / EROWS, NTHR>>>(bfc, out);
}

// round 7
// speedup vs baseline: 4.6177x; 1.0661x over previous
#include <cuda_runtime.h>
#include <cstdint>

#define Bsz 256
#define Tt  200
#define Dd  128
#define Hh  256
#define Oo  128
#define Mm  64
#define RPB 4
#define NBLK (Bsz/RPB)     // 64 scan CTAs
#define NTHR 256
#define SCTH 512           // scan threads: 4 k-groups x 128 h-threads
#define SGRP 4
#define RESG 8             // resident k-slices per group
#define RES_K (SGRP*RESG)  // 32
#define KPAD 272           // 256 k's + 16 zero pad for prefetch overrun
#define BT  (Bsz*Tt)       // 51200
#define RPP 16             // bt-rows per G-precompute CTA
#define EROWS 32           // bt-rows per epilogue CTA

typedef unsigned long long u64;

// ---------------- device globals (no allocs allowed) ----------------
__device__ __align__(16) float4 g_A4 [KPAD * 256];   // [k][h] = (Ai,Af,Ao,Ac)[h][k], k indexes [z|zp]
__device__ __align__(16) float4 g_Bh4[KPAD * 256];   // [k][h] = (Bi,Bf,Bo,Bc)[h][k], k indexes h_prev
__device__ __align__(16) float4 g_bias4[256];        // folded gate biases
__device__ float  g_Wqh[64 * 256];                   // Wq_h = Wq[:,256:384] @ Wfc   [m][hc]
__device__ float  g_bqe[64];                         // bq + Wq[:,256:] @ bfc
__device__ __align__(8) float2 g_WfcT2[128 * 128];   // [hp][o] = (Wfc[o][2hp], Wfc[o][2hp+1])
__device__ float  g_wzd[128], g_wzpd[128];
__device__ __align__(16) float4 g_G4[(long)BT * 256];// 200 MB: precomputed A@[z,zp]+bias
__device__ float  g_H [(long)BT * 256];              // 50 MB: h_t for the epilogue

// ---------------- helpers ----------------
__device__ __forceinline__ float fast_sigmoid(float x) { return 1.0f / (1.0f + __expf(-x)); }
__device__ __forceinline__ float fast_tanh(float x)    { return 1.0f - 2.0f / (__expf(2.0f * x) + 1.0f); }
__device__ __forceinline__ u64 pack2(float lo, float hi) {
    u64 r; asm("mov.b64 %0, {%1, %2};" : "=l"(r) : "f"(lo), "f"(hi)); return r;
}
__device__ __forceinline__ u64 dup2(float v) {
    u64 r; asm("mov.b64 %0, {%1, %1};" : "=l"(r) : "f"(v)); return r;
}
__device__ __forceinline__ void unpack2(u64 v, float& lo, float& hi) {
    asm("mov.b64 {%0, %1}, %2;" : "=f"(lo), "=f"(hi) : "l"(v));
}
__device__ __forceinline__ void fma2(u64& d, u64 a, u64 b) {
    asm("fma.rn.f32x2 %0, %1, %2, %0;" : "+l"(d) : "l"(a), "l"(b));
}
__device__ __forceinline__ u64 add2(u64 a, u64 b) {
    u64 r; asm("add.rn.f32x2 %0, %1, %2;" : "=l"(r) : "l"(a), "l"(b)); return r;
}
// L2-cached (L1-bypassing) 16B load as two packed u64 lanes
__device__ __forceinline__ ulonglong2 ldcg_v2(const ulonglong2* p) {
    ulonglong2 v;
    asm("ld.global.cg.v2.b64 {%0, %1}, [%2];" : "=l"(v.x), "=l"(v.y) : "l"(p));
    return v;
}

// ================= prep1: Wq_h = Wq_xi @ Wfc ; bq_eff =================
__global__ void prep1_kernel(const float* __restrict__ Wq, const float* __restrict__ Wfc,
                             const float* __restrict__ bq, const float* __restrict__ bfc)
{
    int m = blockIdx.x, hc = threadIdx.x;     // grid 64, block 256
    float s = 0.0f;
    for (int o = 0; o < 128; o++)
        s = fmaf(Wq[m * 384 + 256 + o], Wfc[o * 256 + hc], s);
    g_Wqh[m * 256 + hc] = s;
    if (hc == 0) {
        float s2 = bq[m];
        for (int o = 0; o < 128; o++)
            s2 = fmaf(Wq[m * 384 + 256 + o], bfc[o], s2);
        g_bqe[m] = s2;
    }
}

// ================= prep2: fold A, Bh, biases; misc layouts =================
__global__ void prep2_kernel(const float* __restrict__ Wz, const float* __restrict__ Wzp,
                             const float* __restrict__ Wq,
                             const float* __restrict__ Wi, const float* __restrict__ bi,
                             const float* __restrict__ Wf, const float* __restrict__ bf,
                             const float* __restrict__ Wo, const float* __restrict__ bo,
                             const float* __restrict__ Wc, const float* __restrict__ bc,
                             const float* __restrict__ Wfc)
{
    int k = blockIdx.x, h = threadIdx.x;      // grid KPAD(272), block 256
    if (k < 256) {
        float4 a = make_float4(0.f, 0.f, 0.f, 0.f);
        float4 bh;
        bh.x = Wi[h * 320 + 64 + k];
        bh.y = Wf[h * 320 + 64 + k];
        bh.z = Wo[h * 320 + 64 + k];
        bh.w = Wc[h * 320 + 64 + k];
        for (int m = 0; m < 64; m++) {
            float q  = Wq[m * 384 + k];
            float qh = g_Wqh[m * 256 + k];
            float wi = Wi[h * 320 + m], wf = Wf[h * 320 + m];
            float wo = Wo[h * 320 + m], wc = Wc[h * 320 + m];
            a.x = fmaf(wi, q, a.x);  a.y = fmaf(wf, q, a.y);
            a.z = fmaf(wo, q, a.z);  a.w = fmaf(wc, q, a.w);
            bh.x = fmaf(wi, qh, bh.x); bh.y = fmaf(wf, qh, bh.y);
            bh.z = fmaf(wo, qh, bh.z); bh.w = fmaf(wc, qh, bh.w);
        }
        g_A4 [k * 256 + h] = a;
        g_Bh4[k * 256 + h] = bh;
    } else {
        float4 zz = make_float4(0.f, 0.f, 0.f, 0.f);
        g_A4 [k * 256 + h] = zz;
        g_Bh4[k * 256 + h] = zz;
    }
    if (k == 0) {
        float4 b4 = make_float4(bi[h], bf[h], bo[h], bc[h]);
        for (int m = 0; m < 64; m++) {
            float e = g_bqe[m];
            b4.x = fmaf(Wi[h * 320 + m], e, b4.x);
            b4.y = fmaf(Wf[h * 320 + m], e, b4.y);
            b4.z = fmaf(Wo[h * 320 + m], e, b4.z);
            b4.w = fmaf(Wc[h * 320 + m], e, b4.w);
        }
        g_bias4[h] = b4;
    }
    if (k == 1 && h < 128) {
        g_wzd[h]  = Wz[h * 128 + h];
        g_wzpd[h] = Wzp[h * 128 + h];
    }
    if (k < 128 && h < 128)   // WfcT2[hp=k][o=h]
        g_WfcT2[k * 128 + h] = make_float2(Wfc[h * 256 + 2 * k], Wfc[h * 256 + 2 * k + 1]);
}

// ================= G precompute: G = A @ [z,zp] + bias, all (b,t) in parallel ==========
__global__ __launch_bounds__(NTHR) void gpre_kernel(
    const float* __restrict__ inp, const float* __restrict__ xmean,
    const float* __restrict__ bz,  const float* __restrict__ bzp)
{
    __shared__ __align__(16) u64 u2dup[RPP * 256];   // 32 KB, (v,v) duplicated
    __shared__ float s_wzd[128], s_bz[128], s_wzpd[128], s_bzp[128];

    const int tid = threadIdx.x;
    const int bt0 = blockIdx.x * RPP;                 // grid = BT/RPP = 3200

    if (tid < 128) {
        s_wzd[tid] = g_wzd[tid];   s_bz[tid]  = bz[tid];
        s_wzpd[tid] = g_wzpd[tid]; s_bzp[tid] = bzp[tid];
    }
    __syncthreads();

    const long cs = (long)Tt * Dd;
    for (int e = tid; e < RPP * 128; e += NTHR) {
        int row = e >> 7, j = e & 127;
        int bt = bt0 + row, b = bt / Tt, t = bt - b * Tt;
        long base = ((long)b * 6 * Tt + t) * (long)Dd + j;
        float x   = inp[base];
        float xl  = inp[base + 1 * cs];
        float mk  = inp[base + 2 * cs];
        float dl  = inp[base + 3 * cs];
        float xlb = inp[base + 4 * cs];
        float dlb = inp[base + 5 * cs];
        float xm  = xmean[((long)b * Tt + t) * (long)Dd + j];
        float dz  = __expf(-fmaxf(fmaf(dl,  s_wzd[j],  s_bz[j]),  0.0f));
        float dzp = __expf(-fmaxf(fmaf(dlb, s_wzpd[j], s_bzp[j]), 0.0f));
        float z   = mk * x + (1.0f - mk) * (dz  * xl  + (1.0f - dz)  * xm);
        float zp  = mk * x + (1.0f - mk) * (dzp * xlb + (1.0f - dzp) * xm);
        u2dup[row * 256 + j]       = dup2(z);
        u2dup[row * 256 + 128 + j] = dup2(zp);
    }
    __syncthreads();

    u64 aif[RPP], aoc[RPP];
    {
        float4 b4 = g_bias4[tid];
#pragma unroll
        for (int r = 0; r < RPP; r++) { aif[r] = pack2(b4.x, b4.y); aoc[r] = pack2(b4.z, b4.w); }
    }
    const ulonglong2* __restrict__ wg = reinterpret_cast<const ulonglong2*>(g_A4) + tid;
    ulonglong2 wb[8];
#pragma unroll
    for (int i = 0; i < 8; i++) wb[i] = ldcg_v2(wg + i * 256);
#pragma unroll 1
    for (int k0 = 0; k0 < 256; k0 += 8) {
#pragma unroll
        for (int i = 0; i < 8; i += 2) {
            ulonglong2 w0 = wb[i], w1 = wb[i + 1];
            wb[i]     = ldcg_v2(wg + (k0 + 8 + i) * 256);
            wb[i + 1] = ldcg_v2(wg + (k0 + 9 + i) * 256);
#pragma unroll
            for (int r = 0; r < RPP; r++) {
                ulonglong2 hh = *reinterpret_cast<const ulonglong2*>(&u2dup[r * 256 + k0 + i]);
                fma2(aif[r], w0.x, hh.x); fma2(aoc[r], w0.y, hh.x);
                fma2(aif[r], w1.x, hh.y); fma2(aoc[r], w1.y, hh.y);
            }
        }
    }
#pragma unroll
    for (int r = 0; r < RPP; r++) {
        float gi, gf, go, gc;
        unpack2(aif[r], gi, gf); unpack2(aoc[r], go, gc);
        g_G4[(long)(bt0 + r) * 256 + tid] = make_float4(gi, gf, go, gc);
    }
}

// ================= scan: h_t = lstm(G_t + Bh @ h_{t-1}) =================
// 512 threads = 4 k-groups x 128 h-threads; thread owns h pair (hid, hid+128).
// Per step: every group GEMMs its 64-k range (8 resident + 56 streamed) for both
// h's over 4 rows; groups 1/2 fold in G; all deposit packed partials; after one
// barrier ALL threads share the 4-way reduce + activations + h publish.
__global__ __launch_bounds__(SCTH, 1) void scan_kernel()
{
    extern __shared__ __align__(16) char smraw[];
    ulonglong2* resW = reinterpret_cast<ulonglong2*>(smraw);               // [RES_K][256]   131072 B
    u64* hdup = reinterpret_cast<u64*>(smraw + RES_K * 256 * 16);          // [2][RPB][256]   16384 B
    u64* part = reinterpret_cast<u64*>(smraw + RES_K * 256 * 16 + 16384);  // [4][RPB][256][2] 65536 B

    const int tid = threadIdx.x;
    const int g   = tid >> 7;          // k-group 0..3
    const int hid = tid & 127;
    const int h0  = hid, h1 = hid + 128;
    const int b0  = blockIdx.x * RPB;
    const int kb  = g << 6;            // group k-base: 0,64,128,192

    // resident Bh slices: slice s -> global k = 64*(s>>3) + (s&7)
    for (int i = tid; i < RES_K * 256; i += SCTH) {
        int s = i >> 8, h = i & 255;
        int kg = ((s >> 3) << 6) + (s & 7);
        resW[i] = reinterpret_cast<const ulonglong2*>(g_Bh4)[kg * 256 + h];
    }
    for (int i = tid; i < 2 * RPB * 256; i += SCTH) hdup[i] = 0ull;        // h0 = 0

    // reduce-stage state: this thread owns (rows tid>>8 and (tid>>8)+2) at h=tid&255
    float c_reg[2] = {0.0f, 0.0f};

    __syncthreads();

    const ulonglong2* __restrict__ wg0 = reinterpret_cast<const ulonglong2*>(g_Bh4) + h0;
    const ulonglong2* __restrict__ wg1 = reinterpret_cast<const ulonglong2*>(g_Bh4) + h1;
    const ulonglong2* __restrict__ rw0 = resW + (g * RESG) * 256 + h0;
    const ulonglong2* __restrict__ rw1 = resW + (g * RESG) * 256 + h1;
    const float4* __restrict__ G4 = g_G4;

    for (int t = 0; t < Tt; t++) {
        const int cur = t & 1, prv = cur ^ 1;
        const u64* hp = hdup + prv * (RPB * 256);

        // groups 1,2 issue G loads now; consumed at deposit (GEMM hides latency)
        float4 gvl[RPB];
        if (g == 1) {
#pragma unroll
            for (int r = 0; r < RPB; r++) gvl[r] = G4[((long)(b0 + r) * Tt + t) * 256 + h0];
        } else if (g == 2) {
#pragma unroll
            for (int r = 0; r < RPB; r++) gvl[r] = G4[((long)(b0 + r) * Tt + t) * 256 + h1];
        }

        u64 aif0[RPB], aoc0[RPB], aif1[RPB], aoc1[RPB];
#pragma unroll
        for (int r = 0; r < RPB; r++) { aif0[r] = 0ull; aoc0[r] = 0ull; aif1[r] = 0ull; aoc1[r] = 0ull; }

        // prefetch first 4 streamed k's (k = kb+8 .. kb+11), both h's
        ulonglong2 wb[8];
#pragma unroll
        for (int i = 0; i < 4; i++) {
            wb[2 * i]     = ldcg_v2(wg0 + (kb + RESG + i) * 256);
            wb[2 * i + 1] = ldcg_v2(wg1 + (kb + RESG + i) * 256);
        }

        // ---- resident part: 8 k ----
#pragma unroll
        for (int j = 0; j < RESG; j += 2) {
            ulonglong2 wa0 = rw0[j * 256],     wa1 = rw1[j * 256];
            ulonglong2 wb0 = rw0[(j + 1) * 256], wb1 = rw1[(j + 1) * 256];
#pragma unroll
            for (int r = 0; r < RPB; r++) {
                ulonglong2 hh = *reinterpret_cast<const ulonglong2*>(&hp[r * 256 + kb + j]);
                fma2(aif0[r], wa0.x, hh.x); fma2(aoc0[r], wa0.y, hh.x);
                fma2(aif1[r], wa1.x, hh.x); fma2(aoc1[r], wa1.y, hh.x);
                fma2(aif0[r], wb0.x, hh.y); fma2(aoc0[r], wb0.y, hh.y);
                fma2(aif1[r], wb1.x, hh.y); fma2(aoc1[r], wb1.y, hh.y);
            }
        }

        // ---- streamed part: 56 k, 14 blocks of 4, depth-4 pipeline ----
#pragma unroll 1
        for (int k0 = kb + RESG; k0 < kb + 64; k0 += 4) {
#pragma unroll
            for (int i = 0; i < 4; i += 2) {
                ulonglong2 wa0 = wb[2 * i],     wa1 = wb[2 * i + 1];
                ulonglong2 wc0 = wb[2 * i + 2], wc1 = wb[2 * i + 3];
                wb[2 * i]     = ldcg_v2(wg0 + (k0 + 4 + i) * 256);   // pad covers overrun
                wb[2 * i + 1] = ldcg_v2(wg1 + (k0 + 4 + i) * 256);
                wb[2 * i + 2] = ldcg_v2(wg0 + (k0 + 5 + i) * 256);
                wb[2 * i + 3] = ldcg_v2(wg1 + (k0 + 5 + i) * 256);
#pragma unroll
                for (int r = 0; r < RPB; r++) {
                    ulonglong2 hh = *reinterpret_cast<const ulonglong2*>(&hp[r * 256 + k0 + i]);
                    fma2(aif0[r], wa0.x, hh.x); fma2(aoc0[r], wa0.y, hh.x);
                    fma2(aif1[r], wa1.x, hh.x); fma2(aoc1[r], wa1.y, hh.x);
                    fma2(aif0[r], wc0.x, hh.y); fma2(aoc0[r], wc0.y, hh.y);
                    fma2(aif1[r], wc1.x, hh.y); fma2(aoc1[r], wc1.y, hh.y);
                }
            }
        }

        // ---- fold G, deposit partials ----
        if (g == 1) {
#pragma unroll
            for (int r = 0; r < RPB; r++) {
                aif0[r] = add2(aif0[r], pack2(gvl[r].x, gvl[r].y));
                aoc0[r] = add2(aoc0[r], pack2(gvl[r].z, gvl[r].w));
            }
        } else if (g == 2) {
#pragma unroll
            for (int r = 0; r < RPB; r++) {
                aif1[r] = add2(aif1[r], pack2(gvl[r].x, gvl[r].y));
                aoc1[r] = add2(aoc1[r], pack2(gvl[r].z, gvl[r].w));
            }
        }
#pragma unroll
        for (int r = 0; r < RPB; r++) {
            ulonglong2 p0; p0.x = aif0[r]; p0.y = aoc0[r];
            ulonglong2 p1; p1.x = aif1[r]; p1.y = aoc1[r];
            *reinterpret_cast<ulonglong2*>(&part[((g * RPB + r) * 256 + h0) * 2]) = p0;
            *reinterpret_cast<ulonglong2*>(&part[((g * RPB + r) * 256 + h1) * 2]) = p1;
        }
        __syncthreads();

        // ---- all threads: 4-way reduce, activations, publish ----
        {
            const int hh_ = tid & 255;
            const int rb_ = tid >> 8;           // 0 or 1
#pragma unroll
            for (int q = 0; q < 2; q++) {
                const int rr = rb_ + 2 * q;
                ulonglong2 p0 = *reinterpret_cast<const ulonglong2*>(&part[((0 * RPB + rr) * 256 + hh_) * 2]);
                ulonglong2 p1 = *reinterpret_cast<const ulonglong2*>(&part[((1 * RPB + rr) * 256 + hh_) * 2]);
                ulonglong2 p2 = *reinterpret_cast<const ulonglong2*>(&part[((2 * RPB + rr) * 256 + hh_) * 2]);
                ulonglong2 p3 = *reinterpret_cast<const ulonglong2*>(&part[((3 * RPB + rr) * 256 + hh_) * 2]);
                u64 tif = add2(add2(p0.x, p1.x), add2(p2.x, p3.x));
                u64 toc = add2(add2(p0.y, p1.y), add2(p2.y, p3.y));
                float ai, afv, ao, ac;
                unpack2(tif, ai, afv); unpack2(toc, ao, ac);
                float ig = fast_sigmoid(ai), fg = fast_sigmoid(afv);
                float og = fast_sigmoid(ao), ct = fast_tanh(ac);
                c_reg[q] = fg * c_reg[q] + ig * ct;
                float hv = og * fast_tanh(c_reg[q]);
                hdup[cur * (RPB * 256) + rr * 256 + hh_] = dup2(hv);
                g_H[((long)(b0 + rr) * Tt + t) * 256 + hh_] = hv;
            }
        }
        __syncthreads();
    }
}

// ================= epilogue: out = H @ Wfc^T + bfc (fully parallel) =================
__global__ __launch_bounds__(NTHR) void epi_kernel(const float* __restrict__ bfc,
                                                   float* __restrict__ out)
{
    __shared__ __align__(16) float hs[EROWS * 256];   // 32 KB
    const int tid = threadIdx.x;
    const int bt0 = blockIdx.x * EROWS;               // grid = BT/EROWS = 1600

    for (int e = tid; e < EROWS * 256; e += NTHR)
        hs[e] = g_H[(long)bt0 * 256 + e];
    __syncthreads();

    const int o  = tid & 127;
    const int rb = (tid >> 7) * 16;                   // rows rb .. rb+15
    u64 acc[16];
#pragma unroll
    for (int r = 0; r < 16; r++) acc[r] = 0ull;

    const u64* __restrict__ w2 = reinterpret_cast<const u64*>(g_WfcT2) + o;
#pragma unroll 4
    for (int hpi = 0; hpi < 128; hpi++) {
        u64 w = w2[hpi * 128];
#pragma unroll
        for (int r = 0; r < 16; r++)
            fma2(acc[r], w, *reinterpret_cast<const u64*>(&hs[(rb + r) * 256 + 2 * hpi]));
    }
    const float bo_ = bfc[o];
#pragma unroll
    for (int r = 0; r < 16; r++) {
        float x0, x1; unpack2(acc[r], x0, x1);
        out[(long)(bt0 + rb + r) * Oo + o] = bo_ + x0 + x1;
    }
}

// ================= launch =================
#define SCAN_SMEM (RES_K*256*16 + 2*RPB*256*8 + SGRP*RPB*256*2*8)   // 131072+16384+65536 = 212992

extern "C" void kernel_launch(void* const* d_in, const int* in_sizes, int n_in,
                              void* d_out, int out_size)
{
    const float* inp   = (const float*)d_in[0];
    const float* xmean = (const float*)d_in[1];
    const float* Wz    = (const float*)d_in[2];
    const float* bz    = (const float*)d_in[3];
    const float* Wzp   = (const float*)d_in[4];
    const float* bzp   = (const float*)d_in[5];
    const float* Wq    = (const float*)d_in[6];
    const float* bq    = (const float*)d_in[7];
    const float* Wi    = (const float*)d_in[8];
    const float* bi    = (const float*)d_in[9];
    const float* Wf    = (const float*)d_in[10];
    const float* bf    = (const float*)d_in[11];
    const float* Wo    = (const float*)d_in[12];
    const float* bo    = (const float*)d_in[13];
    const float* Wc    = (const float*)d_in[14];
    const float* bc    = (const float*)d_in[15];
    const float* Wfc   = (const float*)d_in[16];
    const float* bfc   = (const float*)d_in[17];
    float* out = (float*)d_out;

    static int attr_done = 0;
    if (!attr_done) {
        cudaFuncSetAttribute(scan_kernel, cudaFuncAttributeMaxDynamicSharedMemorySize, SCAN_SMEM);
        attr_done = 1;
    }

    prep1_kernel<<<64, 256>>>(Wq, Wfc, bq, bfc);
    prep2_kernel<<<KPAD, 256>>>(Wz, Wzp, Wq, Wi, bi, Wf, bf, Wo, bo, Wc, bc, Wfc);
    gpre_kernel<<<BT / RPP, NTHR>>>(inp, xmean, bz, bzp);
    scan_kernel<<<NBLK, SCTH, SCAN_SMEM>>>();
    epi_kernel<<<BT / EROWS, NTHR>>>(bfc, out);
}